// round 5
// baseline (speedup 1.0000x reference)
#include <cuda_runtime.h>

typedef unsigned long long u64;

__device__ __forceinline__ void ffma2(u64 &d, u64 a, u64 b) {
    asm("fma.rn.f32x2 %0, %1, %2, %0;" : "+l"(d) : "l"(a), "l"(b));
}
__device__ __forceinline__ void fscale2(u64 &d, u64 a) {
    asm("mul.rn.f32x2 %0, %0, %1;" : "+l"(d) : "l"(a));
}
__device__ __forceinline__ u64 pack2(float lo, float hi) {
    u64 d; asm("mov.b64 %0, {%1, %2};" : "=l"(d) : "f"(lo), "f"(hi)); return d;
}
__device__ __forceinline__ void unpack2(u64 v, float &lo, float &hi) {
    asm("mov.b64 {%0, %1}, %2;" : "=f"(lo), "=f"(hi) : "l"(v));
}

// ---------------- scratch (device globals; no allocation allowed) ----------
__device__ float g_qT[2 * 4 * 4096 * 32];   // scaled q [b][h][n][d]
__device__ float g_y3a[2 * 256 * 256];      // branch1 y3 [b][c][s]
__device__ float g_y3b[2 * 256 * 1024];     // branch2 y3
__device__ float g_K1[2 * 4 * 512 * 32];    // [b][h][l][d]
__device__ float g_V1[2 * 4 * 512 * 32];
__device__ float g_K2[2 * 4 * 2048 * 32];
__device__ float g_V2[2 * 4 * 2048 * 32];
__device__ float g_cr1[2 * 64 * 512];       // col-resized rpe [b][r][l]
__device__ float g_cr2[2 * 64 * 2048];
__device__ int   g_rbase[4096];
__device__ float g_rw[4096 * 4];

// Keys cubic a=-0.5, jax.image.resize semantics (drop OOB taps, renormalize).
__device__ __forceinline__ void cubic4(float sample, int size, int &base, float *w) {
    int t0 = (int)floorf(sample) - 1;
    float ws[4]; float sum = 0.f;
#pragma unroll
    for (int j = 0; j < 4; j++) {
        int t = t0 + j;
        float xd = fabsf(sample - (float)t);
        float wv;
        if (xd <= 1.f)      wv = ((1.5f * xd - 2.5f) * xd) * xd + 1.f;
        else if (xd < 2.f)  wv = ((-0.5f * xd + 2.5f) * xd - 4.f) * xd + 2.f;
        else                wv = 0.f;
        if (t < 0 || t >= size) wv = 0.f;
        ws[j] = wv; sum += wv;
    }
    float inv = 1.f / sum;
    int nb = t0 < 0 ? 0 : (t0 > size - 4 ? size - 4 : t0);
    base = nb;
    w[0] = w[1] = w[2] = w[3] = 0.f;
#pragma unroll
    for (int j = 0; j < 4; j++) {
        int t = t0 + j;
        if (t >= 0 && t < size) w[t - nb] = ws[j] * inv;
    }
}

__global__ void rowtab_k() {
    int n = blockIdx.x * 256 + threadIdx.x;
    if (n >= 4096) return;
    float sample = (n + 0.5f) * 0.015625f - 0.5f;
    int base; float w[4];
    cubic4(sample, 64, base, w);
    g_rbase[n] = base;
#pragma unroll
    for (int j = 0; j < 4; j++) g_rw[n * 4 + j] = w[j];
}

__global__ void colres_k(const float * __restrict__ rpe, int Lc, int branch) {
    int idx = blockIdx.x * blockDim.x + threadIdx.x;
    if (idx >= 2 * 64 * Lc) return;
    int l = idx % Lc;
    int r = (idx / Lc) & 63;
    int b = idx / (Lc * 64);
    float sample = (l + 0.5f) * (64.f / (float)Lc) - 0.5f;
    int base; float w[4];
    cubic4(sample, 64, base, w);
    const float *row = rpe + ((size_t)(b * 2 + branch) * 64 + r) * 64;
    float v = w[0]*row[base] + w[1]*row[base+1] + w[2]*row[base+2] + w[3]*row[base+3];
    (branch ? g_cr2 : g_cr1)[((size_t)b * 64 + r) * Lc + l] = v;
}

// q 1x1 conv, heads 0..3 (cout<128), scaled by 1/sqrt(32), packed [b][h][n][d]
__global__ void __launch_bounds__(256) qgemm_k(const float * __restrict__ x,
                                               const float * __restrict__ qw,
                                               const float * __restrict__ qb) {
    int b = blockIdx.z, ct = blockIdx.y, nt = blockIdx.x;
    __shared__ float Xs[4096], Ws[4096];
    int tid = threadIdx.x, tn = tid & 15, tc = tid >> 4;
    float acc[4][4] = {};
    const float *xb = x + (size_t)(b * 256) * 4096 + nt * 64;
    for (int cc = 0; cc < 4; cc++) {
        __syncthreads();
        for (int i = tid; i < 4096; i += 256) {
            int rr = i >> 6, c2 = i & 63;
            Xs[i] = xb[(size_t)(cc * 64 + rr) * 4096 + c2];
            Ws[i] = qw[(size_t)(ct * 64 + rr) * 256 + cc * 64 + c2];
        }
        __syncthreads();
#pragma unroll 4
        for (int ci = 0; ci < 64; ci++) {
            float4 xv = *(const float4*)&Xs[ci * 64 + tn * 4];
            float xa[4] = {xv.x, xv.y, xv.z, xv.w};
#pragma unroll
            for (int k = 0; k < 4; k++) {
                float wv = Ws[(tc * 4 + k) * 64 + ci];
#pragma unroll
                for (int j = 0; j < 4; j++) acc[k][j] = fmaf(wv, xa[j], acc[k][j]);
            }
        }
    }
    const float SCALE = 0.17677669529663687f;
#pragma unroll
    for (int k = 0; k < 4; k++) {
        int co = ct * 64 + tc * 4 + k;
        float bias = qb[co];
        int h = co >> 5, d = co & 31;
#pragma unroll
        for (int j = 0; j < 4; j++) {
            int n = nt * 64 + tn * 4 + j;
            g_qT[((size_t)(b * 4 + h) * 4096 + n) * 32 + d] = (acc[k][j] + bias) * SCALE;
        }
    }
}

// fused per-plane: dwconv(KxK,s,p)+bn1+relu, pw*bn2, local3x3+bias+residual
template <int K, int S, int P, int HO, int BR>
__global__ void __launch_bounds__(256) plane_k(const float * __restrict__ x,
                                               const float * __restrict__ dww,
                                               const float * __restrict__ bn1,
                                               const float * __restrict__ pww,
                                               const float * __restrict__ bn2,
                                               const float * __restrict__ lw,
                                               const float * __restrict__ lb) {
    int b = blockIdx.x >> 8, c = blockIdx.x & 255;
    __shared__ float xs[4096];
    __shared__ float ys[HO * HO];
    __shared__ float wk[K * K];
    int tid = threadIdx.x;
    const float *xp = x + (size_t)(b * 256 + c) * 4096;
    for (int i = tid; i < 4096; i += 256) xs[i] = xp[i];
    if (tid < K * K) wk[tid] = dww[c * K * K + tid];
    float a1 = bn1[c] * rsqrtf(bn1[768 + c] + 1e-5f);
    float c1 = bn1[256 + c] - bn1[512 + c] * a1;
    float s2 = bn2[c] * rsqrtf(bn2[768 + c] + 1e-5f);
    float A2 = pww[c] * s2;
    float B2 = bn2[256 + c] - bn2[512 + c] * s2;
    __syncthreads();
    for (int o = tid; o < HO * HO; o += 256) {
        int oy = o / HO, ox = o - oy * HO;
        float acc = 0.f;
#pragma unroll
        for (int ky = 0; ky < K; ky++) {
            int iy = oy * S - P + ky;
            if (iy < 0 || iy > 63) continue;
#pragma unroll
            for (int kx = 0; kx < K; kx++) {
                int ix = ox * S - P + kx;
                if (ix >= 0 && ix <= 63) acc = fmaf(wk[ky * K + kx], xs[iy * 64 + ix], acc);
            }
        }
        float y1 = fmaxf(fmaf(acc, a1, c1), 0.f);
        ys[o] = fmaf(y1, A2, B2);
    }
    __syncthreads();
    float l9[9];
#pragma unroll
    for (int t = 0; t < 9; t++) l9[t] = lw[c * 9 + t];
    float lbv = lb[c];
    float *outp = (BR ? g_y3b : g_y3a) + (size_t)(b * 256 + c) * (HO * HO);
    for (int o = tid; o < HO * HO; o += 256) {
        int oy = o / HO, ox = o - oy * HO;
        float acc = lbv;
#pragma unroll
        for (int ky = 0; ky < 3; ky++) {
            int iy = oy - 1 + ky;
            if (iy < 0 || iy >= HO) continue;
#pragma unroll
            for (int kx = 0; kx < 3; kx++) {
                int ix = ox - 1 + kx;
                if (ix >= 0 && ix < HO) acc = fmaf(l9[ky * 3 + kx], ys[iy * HO + ix], acc);
            }
        }
        outp[o] = acc + ys[o];
    }
}

// kv 1x1 conv (512 couts) over y3; epilogue packs K/V as [b][h][l][32]
__global__ void __launch_bounds__(256) kvgemm_k(const float * __restrict__ w,
                                                const float * __restrict__ bias,
                                                int branch) {
    int b = blockIdx.z, ct = blockIdx.y, st = blockIdx.x;
    int HW = branch ? 1024 : 256;
    const float *y3 = branch ? g_y3b : g_y3a;
    float *Kp = branch ? g_K2 : g_K1;
    float *Vp = branch ? g_V2 : g_V1;
    __shared__ float Xs[4096], Ws[4096];
    int tid = threadIdx.x, tn = tid & 15, tc = tid >> 4;
    float acc[4][4] = {};
    const float *xb = y3 + (size_t)b * 256 * HW + st * 64;
    for (int cc = 0; cc < 4; cc++) {
        __syncthreads();
        for (int i = tid; i < 4096; i += 256) {
            int rr = i >> 6, c2 = i & 63;
            Xs[i] = xb[(size_t)(cc * 64 + rr) * HW + c2];
            Ws[i] = w[(size_t)(ct * 64 + rr) * 256 + cc * 64 + c2];
        }
        __syncthreads();
#pragma unroll 4
        for (int ci = 0; ci < 64; ci++) {
            float4 xv = *(const float4*)&Xs[ci * 64 + tn * 4];
            float xa[4] = {xv.x, xv.y, xv.z, xv.w};
#pragma unroll
            for (int k = 0; k < 4; k++) {
                float wv = Ws[(tc * 4 + k) * 64 + ci];
#pragma unroll
                for (int j = 0; j < 4; j++) acc[k][j] = fmaf(wv, xa[j], acc[k][j]);
            }
        }
    }
    int L = 2 * HW;
#pragma unroll
    for (int k = 0; k < 4; k++) {
        int co = ct * 64 + tc * 4 + k;
        float bv = bias[co];
        int cm = co & 255, h = cm >> 6, d = (cm & 63) >> 1, e = cm & 1;
        float *dst = (co < 256) ? Kp : Vp;
#pragma unroll
        for (int j = 0; j < 4; j++) {
            int s = st * 64 + tn * 4 + j;
            dst[((size_t)(b * 4 + h) * L + e * HW + s) * 32 + d] = acc[k][j] + bv;
        }
    }
}

// flash attention: CTA = 4 heads x 32 query rows, warp-private tiles, TL=16
__global__ void __launch_bounds__(128) attn_k(float * __restrict__ out) {
    int b = blockIdx.z, br = blockIdx.y, ntile = blockIdx.x;
    int L = br ? 2048 : 512;
    const float *Kp = br ? g_K2 : g_K1;
    const float *Vp = br ? g_V2 : g_V1;
    const float *cr = br ? g_cr2 : g_cr1;
    int tid = threadIdx.x, h = tid >> 5, lane = tid & 31;
    int n = ntile * 32 + lane;

    __shared__ __align__(16) float KS[4][16 * 32];
    __shared__ __align__(16) float VS[4][16 * 32];
    __shared__ float CRS[4][5 * 16];

    // q row (pre-scaled)
    u64 q2[16];
    const u64 *qp = (const u64*)(g_qT + ((size_t)(b * 4 + h) * 4096 + n) * 32);
#pragma unroll
    for (int t = 0; t < 16; t++) q2[t] = qp[t];

    // bicubic row weights
    int rb = g_rbase[n];
    float w0 = g_rw[n * 4 + 0], w1 = g_rw[n * 4 + 1];
    float w2 = g_rw[n * 4 + 2], w3 = g_rw[n * 4 + 3];
    int r0 = g_rbase[ntile * 32];
    int rr = rb - r0;   // 0 or 1

    const float *Kh = Kp + (size_t)(b * 4 + h) * L * 32;
    const float *Vh = Vp + (size_t)(b * 4 + h) * L * 32;
    const float *crb = cr + (size_t)b * 64 * L;

    float m = -1e30f, sum = 0.f;
    u64 O2[16];
#pragma unroll
    for (int t = 0; t < 16; t++) O2[t] = pack2(0.f, 0.f);

    for (int l0 = 0; l0 < L; l0 += 16) {
        // per-warp tile loads
        float4 *ks4 = (float4*)&KS[h][0];
        float4 *vs4 = (float4*)&VS[h][0];
        const float4 *kg = (const float4*)(Kh + (size_t)l0 * 32);
        const float4 *vg = (const float4*)(Vh + (size_t)l0 * 32);
#pragma unroll
        for (int t = 0; t < 4; t++) {
            ks4[lane + 32 * t] = kg[lane + 32 * t];
            vs4[lane + 32 * t] = vg[lane + 32 * t];
        }
        for (int i = lane; i < 80; i += 32) {
            int r = r0 + i / 16; if (r > 63) r = 63;
            CRS[h][i] = crb[(size_t)r * L + l0 + (i & 15)];
        }
        __syncwarp();

        float s[16];
#pragma unroll
        for (int jj = 0; jj < 16; jj++) {
            u64 a0 = pack2(0.f, 0.f), a1 = pack2(0.f, 0.f);
            const u64 *k2 = (const u64*)&KS[h][jj * 32];
#pragma unroll
            for (int t = 0; t < 8; t++) {
                ffma2(a0, q2[2 * t],     k2[2 * t]);
                ffma2(a1, q2[2 * t + 1], k2[2 * t + 1]);
            }
            float x0, x1, y0, y1;
            unpack2(a0, x0, x1); unpack2(a1, y0, y1);
            float sc = (x0 + y0) + (x1 + y1);
            float rp = w0 * CRS[h][rr * 16 + jj] + w1 * CRS[h][(rr + 1) * 16 + jj]
                     + w2 * CRS[h][(rr + 2) * 16 + jj] + w3 * CRS[h][(rr + 3) * 16 + jj];
            s[jj] = sc + rp;
        }
        float mt = s[0];
#pragma unroll
        for (int jj = 1; jj < 16; jj++) mt = fmaxf(mt, s[jj]);
        float nm = fmaxf(m, mt);
        float f = __expf(m - nm);
        sum *= f;
        u64 f2 = pack2(f, f);
#pragma unroll
        for (int t = 0; t < 16; t++) fscale2(O2[t], f2);
        m = nm;
#pragma unroll
        for (int jj = 0; jj < 16; jj++) {
            float p = __expf(s[jj] - nm);
            sum += p;
            u64 p2 = pack2(p, p);
            const u64 *v2 = (const u64*)&VS[h][jj * 32];
#pragma unroll
            for (int t = 0; t < 16; t++) ffma2(O2[t], p2, v2[t]);
        }
        __syncwarp();
    }

    float inv = 1.f / sum;
    int ny = n >> 6, nx = n & 63;
    float4 *op = (float4*)(out + (((size_t)(b * 256 + h * 64 + ny) * 64 + nx) * 64 + br * 32));
#pragma unroll
    for (int t = 0; t < 8; t++) {
        float a, bb, c, d;
        unpack2(O2[2 * t], a, bb);
        unpack2(O2[2 * t + 1], c, d);
        op[t] = make_float4(a * inv, bb * inv, c * inv, d * inv);
    }
}

extern "C" void kernel_launch(void* const* d_in, const int* in_sizes, int n_in,
                              void* d_out, int out_size) {
    const float *x    = (const float*)d_in[0];
    const float *rpe  = (const float*)d_in[1];
    const float *q_w  = (const float*)d_in[2];
    const float *q_b  = (const float*)d_in[3];
    const float *kv_w = (const float*)d_in[4];
    const float *kv_b = (const float*)d_in[5];
    const float *dw1  = (const float*)d_in[6];
    const float *bn11 = (const float*)d_in[7];
    const float *pw1  = (const float*)d_in[8];
    const float *bn12 = (const float*)d_in[9];
    const float *dw2  = (const float*)d_in[10];
    const float *bn21 = (const float*)d_in[11];
    const float *pw2  = (const float*)d_in[12];
    const float *bn22 = (const float*)d_in[13];
    const float *lw   = (const float*)d_in[14];
    const float *lb   = (const float*)d_in[15];
    float *out = (float*)d_out;

    rowtab_k<<<16, 256>>>();
    colres_k<<<256, 256>>>(rpe, 512, 0);
    colres_k<<<1024, 256>>>(rpe, 2048, 1);
    qgemm_k<<<dim3(64, 2, 2), 256>>>(x, q_w, q_b);
    plane_k<7, 4, 3, 16, 0><<<512, 256>>>(x, dw1, bn11, pw1, bn12, lw, lb);
    plane_k<5, 2, 2, 32, 1><<<512, 256>>>(x, dw2, bn21, pw2, bn22, lw, lb);
    kvgemm_k<<<dim3(4, 8, 2), 256>>>(kv_w, kv_b, 0);
    kvgemm_k<<<dim3(16, 8, 2), 256>>>(kv_w, kv_b, 1);
    attn_k<<<dim3(128, 2, 2), 128>>>(out);
}

// round 6
// speedup vs baseline: 1.4616x; 1.4616x over previous
#include <cuda_runtime.h>

typedef unsigned long long u64;

__device__ __forceinline__ void ffma2(u64 &d, u64 a, u64 b) {
    asm("fma.rn.f32x2 %0, %1, %2, %0;" : "+l"(d) : "l"(a), "l"(b));
}
__device__ __forceinline__ void fscale2(u64 &d, u64 a) {
    asm("mul.rn.f32x2 %0, %0, %1;" : "+l"(d) : "l"(a));
}
__device__ __forceinline__ u64 pack2(float lo, float hi) {
    u64 d; asm("mov.b64 %0, {%1, %2};" : "=l"(d) : "f"(lo), "f"(hi)); return d;
}
__device__ __forceinline__ void unpack2(u64 v, float &lo, float &hi) {
    asm("mov.b64 {%0, %1}, %2;" : "=f"(lo), "=f"(hi) : "l"(v));
}
__device__ __forceinline__ void cpa16(void* s, const void* g) {
    unsigned sa = (unsigned)__cvta_generic_to_shared(s);
    asm volatile("cp.async.ca.shared.global [%0], [%1], 16;" :: "r"(sa), "l"(g));
}
__device__ __forceinline__ void cpcommit() { asm volatile("cp.async.commit_group;"); }
__device__ __forceinline__ void cpwait1() { asm volatile("cp.async.wait_group 1;"); }
__device__ __forceinline__ void cpwait0() { asm volatile("cp.async.wait_group 0;"); }

// ---------------- scratch ----------------
__device__ float g_qT[2 * 4 * 4096 * 32];
__device__ float g_y3a[2 * 256 * 256];
__device__ float g_y3b[2 * 256 * 1024];
__device__ float g_K1[2 * 4 * 512 * 32];
__device__ float g_V1[2 * 4 * 512 * 32];
__device__ float g_K2[2 * 4 * 2048 * 32];
__device__ float g_V2[2 * 4 * 2048 * 32];
__device__ float g_cr1[2 * 64 * 512];
__device__ float g_cr2[2 * 64 * 2048];
__device__ int   g_rbase[4096];
__device__ float g_rw[4096 * 4];
// flash partials: layout [b][h][chunk][t<8][n][4]
__device__ float g_pO1[2 * 4 * 2 * 8 * 4096 * 4];
__device__ float g_pO2[2 * 4 * 8 * 8 * 4096 * 4];
__device__ float g_pm1[2 * 4 * 2 * 4096];
__device__ float g_ps1[2 * 4 * 2 * 4096];
__device__ float g_pm2[2 * 4 * 8 * 4096];
__device__ float g_ps2[2 * 4 * 8 * 4096];

// Keys cubic a=-0.5, jax.image.resize semantics (drop OOB taps, renormalize).
__device__ __forceinline__ void cubic4(float sample, int size, int &base, float *w) {
    int t0 = (int)floorf(sample) - 1;
    float ws[4]; float sum = 0.f;
#pragma unroll
    for (int j = 0; j < 4; j++) {
        int t = t0 + j;
        float xd = fabsf(sample - (float)t);
        float wv;
        if (xd <= 1.f)      wv = ((1.5f * xd - 2.5f) * xd) * xd + 1.f;
        else if (xd < 2.f)  wv = ((-0.5f * xd + 2.5f) * xd - 4.f) * xd + 2.f;
        else                wv = 0.f;
        if (t < 0 || t >= size) wv = 0.f;
        ws[j] = wv; sum += wv;
    }
    float inv = 1.f / sum;
    int nb = t0 < 0 ? 0 : (t0 > size - 4 ? size - 4 : t0);
    base = nb;
    w[0] = w[1] = w[2] = w[3] = 0.f;
#pragma unroll
    for (int j = 0; j < 4; j++) {
        int t = t0 + j;
        if (t >= 0 && t < size) w[t - nb] = ws[j] * inv;
    }
}

__global__ void rowtab_k() {
    int n = blockIdx.x * 256 + threadIdx.x;
    if (n >= 4096) return;
    float sample = (n + 0.5f) * 0.015625f - 0.5f;
    int base; float w[4];
    cubic4(sample, 64, base, w);
    g_rbase[n] = base;
#pragma unroll
    for (int j = 0; j < 4; j++) g_rw[n * 4 + j] = w[j];
}

__global__ void colres_k(const float * __restrict__ rpe, int Lc, int branch) {
    int idx = blockIdx.x * blockDim.x + threadIdx.x;
    if (idx >= 2 * 64 * Lc) return;
    int l = idx % Lc;
    int r = (idx / Lc) & 63;
    int b = idx / (Lc * 64);
    float sample = (l + 0.5f) * (64.f / (float)Lc) - 0.5f;
    int base; float w[4];
    cubic4(sample, 64, base, w);
    const float *row = rpe + ((size_t)(b * 2 + branch) * 64 + r) * 64;
    float v = w[0]*row[base] + w[1]*row[base+1] + w[2]*row[base+2] + w[3]*row[base+3];
    (branch ? g_cr2 : g_cr1)[((size_t)b * 64 + r) * Lc + l] = v;
}

// generic 1x1-conv GEMM: 64 cout x 32 cols per CTA, K=256, 128 threads.
// mode 0: q (input x), mode 1: kv branch1 (g_y3a), mode 2: kv branch2 (g_y3b)
__global__ void __launch_bounds__(128) gemm_k(const float * __restrict__ xin,
                                              const float * __restrict__ W,
                                              const float * __restrict__ bias,
                                              int mode) {
    int b = blockIdx.z, ct = blockIdx.y, nt = blockIdx.x;
    const float *X; int HW;
    if (mode == 0)      { X = xin;   HW = 4096; }
    else if (mode == 1) { X = g_y3a; HW = 256;  }
    else                { X = g_y3b; HW = 1024; }
    __shared__ float Xs[64 * 32];
    __shared__ float Ws[64 * 65];
    int tid = threadIdx.x, tn = tid & 7, tc = tid >> 3;
    float acc[4][4] = {};
    const float *xb = X + (size_t)b * 256 * HW + nt * 32;
    for (int cc = 0; cc < 4; cc++) {
        __syncthreads();
        for (int i = tid; i < 2048; i += 128)
            Xs[i] = xb[(size_t)(cc * 64 + (i >> 5)) * HW + (i & 31)];
        for (int i = tid; i < 4096; i += 128) {
            int co = i >> 6, k = i & 63;
            Ws[co * 65 + k] = W[(size_t)(ct * 64 + co) * 256 + cc * 64 + k];
        }
        __syncthreads();
#pragma unroll 4
        for (int ci = 0; ci < 64; ci++) {
            float4 xv = *(const float4*)&Xs[ci * 32 + tn * 4];
            float xa[4] = {xv.x, xv.y, xv.z, xv.w};
#pragma unroll
            for (int k2 = 0; k2 < 4; k2++) {
                float wv = Ws[(tc * 4 + k2) * 65 + ci];
#pragma unroll
                for (int j = 0; j < 4; j++) acc[k2][j] = fmaf(wv, xa[j], acc[k2][j]);
            }
        }
    }
    if (mode == 0) {
        const float SCALE = 0.17677669529663687f;
#pragma unroll
        for (int k2 = 0; k2 < 4; k2++) {
            int co = ct * 64 + tc * 4 + k2;
            float bv = bias[co];
            int h = co >> 5, d = co & 31;
#pragma unroll
            for (int j = 0; j < 4; j++) {
                int n = nt * 32 + tn * 4 + j;
                g_qT[((size_t)(b * 4 + h) * 4096 + n) * 32 + d] = (acc[k2][j] + bv) * SCALE;
            }
        }
    } else {
        int L = 2 * HW;
        float *Kp = (mode == 2) ? g_K2 : g_K1;
        float *Vp = (mode == 2) ? g_V2 : g_V1;
#pragma unroll
        for (int k2 = 0; k2 < 4; k2++) {
            int co = ct * 64 + tc * 4 + k2;
            float bv = bias[co];
            int cm = co & 255, h = cm >> 6, d = (cm & 63) >> 1, e = cm & 1;
            float *dst = (co < 256) ? Kp : Vp;
#pragma unroll
            for (int j = 0; j < 4; j++) {
                int s = nt * 32 + tn * 4 + j;
                dst[((size_t)(b * 4 + h) * L + e * HW + s) * 32 + d] = acc[k2][j] + bv;
            }
        }
    }
}

// fused per-plane: dwconv(KxK,s,p)+bn1+relu, pw*bn2, local3x3+bias+residual
template <int K, int S, int P, int HO, int BR>
__global__ void __launch_bounds__(256) plane_k(const float * __restrict__ x,
                                               const float * __restrict__ dww,
                                               const float * __restrict__ bn1,
                                               const float * __restrict__ pww,
                                               const float * __restrict__ bn2,
                                               const float * __restrict__ lw,
                                               const float * __restrict__ lb) {
    int b = blockIdx.x >> 8, c = blockIdx.x & 255;
    __shared__ float xs[4096];
    __shared__ float ys[HO * HO];
    __shared__ float wk[K * K];
    int tid = threadIdx.x;
    const float *xp = x + (size_t)(b * 256 + c) * 4096;
    for (int i = tid; i < 4096; i += 256) xs[i] = xp[i];
    if (tid < K * K) wk[tid] = dww[c * K * K + tid];
    float a1 = bn1[c] * rsqrtf(bn1[768 + c] + 1e-5f);
    float c1 = bn1[256 + c] - bn1[512 + c] * a1;
    float s2 = bn2[c] * rsqrtf(bn2[768 + c] + 1e-5f);
    float A2 = pww[c] * s2;
    float B2 = bn2[256 + c] - bn2[512 + c] * s2;
    __syncthreads();
    for (int o = tid; o < HO * HO; o += 256) {
        int oy = o / HO, ox = o - oy * HO;
        float acc = 0.f;
#pragma unroll
        for (int ky = 0; ky < K; ky++) {
            int iy = oy * S - P + ky;
            if (iy < 0 || iy > 63) continue;
#pragma unroll
            for (int kx = 0; kx < K; kx++) {
                int ix = ox * S - P + kx;
                if (ix >= 0 && ix <= 63) acc = fmaf(wk[ky * K + kx], xs[iy * 64 + ix], acc);
            }
        }
        float y1 = fmaxf(fmaf(acc, a1, c1), 0.f);
        ys[o] = fmaf(y1, A2, B2);
    }
    __syncthreads();
    float l9[9];
#pragma unroll
    for (int t = 0; t < 9; t++) l9[t] = lw[c * 9 + t];
    float lbv = lb[c];
    float *outp = (BR ? g_y3b : g_y3a) + (size_t)(b * 256 + c) * (HO * HO);
    for (int o = tid; o < HO * HO; o += 256) {
        int oy = o / HO, ox = o - oy * HO;
        float acc = lbv;
#pragma unroll
        for (int ky = 0; ky < 3; ky++) {
            int iy = oy - 1 + ky;
            if (iy < 0 || iy >= HO) continue;
#pragma unroll
            for (int kx = 0; kx < 3; kx++) {
                int ix = ox - 1 + kx;
                if (ix >= 0 && ix < HO) acc = fmaf(l9[ky * 3 + kx], ys[iy * HO + ix], acc);
            }
        }
        outp[o] = acc + ys[o];
    }
}

// flash attention, uniform 256-l work units, cp.async double-buffered tiles.
// grid: 2560 CTAs. u<2048: branch2 (8 chunks); else branch1 (2 chunks).
__global__ void __launch_bounds__(128) attn_k() {
    int u = blockIdx.x;
    int b, br, ntile, chunk;
    if (u < 2048) { br = 1; chunk = u & 7; ntile = (u >> 3) & 127; b = u >> 10; }
    else { int v = u - 2048; br = 0; chunk = v & 1; ntile = (v >> 1) & 127; b = v >> 8; }
    int L = br ? 2048 : 512;
    const float *Kp = br ? g_K2 : g_K1;
    const float *Vp = br ? g_V2 : g_V1;
    const float *cr = br ? g_cr2 : g_cr1;

    int tid = threadIdx.x, h = tid >> 5, lane = tid & 31;
    int n = ntile * 32 + lane;

    __shared__ __align__(16) float KS[4][2][512];
    __shared__ __align__(16) float VS[4][2][512];
    __shared__ __align__(16) float CRS[4][2][80];

    u64 q2[16];
    const u64 *qp = (const u64*)(g_qT + ((size_t)(b * 4 + h) * 4096 + n) * 32);
#pragma unroll
    for (int t = 0; t < 16; t++) q2[t] = qp[t];

    int rb = g_rbase[n];
    float w0 = g_rw[n * 4 + 0], w1 = g_rw[n * 4 + 1];
    float w2 = g_rw[n * 4 + 2], w3 = g_rw[n * 4 + 3];
    int r0 = g_rbase[ntile * 32];
    int rr = rb - r0;   // 0 or 1

    const float *Kh = Kp + (size_t)(b * 4 + h) * L * 32;
    const float *Vh = Vp + (size_t)(b * 4 + h) * L * 32;
    const float *crb = cr + (size_t)b * 64 * L;
    int l0base = chunk * 256;

    float m = -1e30f, sum = 0.f;
    u64 O2[16];
#pragma unroll
    for (int t = 0; t < 16; t++) O2[t] = pack2(0.f, 0.f);

    auto stage = [&](int buf, int l0) {
        const float4 *kg = (const float4*)(Kh + (size_t)l0 * 32);
        const float4 *vg = (const float4*)(Vh + (size_t)l0 * 32);
#pragma unroll
        for (int t = 0; t < 4; t++) {
            cpa16(&KS[h][buf][(lane + 32 * t) * 4], kg + lane + 32 * t);
            cpa16(&VS[h][buf][(lane + 32 * t) * 4], vg + lane + 32 * t);
        }
        if (lane < 20) {
            int r = r0 + (lane >> 2); if (r > 63) r = 63;
            cpa16(&CRS[h][buf][(lane >> 2) * 16 + 4 * (lane & 3)],
                  crb + (size_t)r * L + l0 + 4 * (lane & 3));
        }
        cpcommit();
    };

    stage(0, l0base);
    int cur = 0;
    for (int ti = 0; ti < 16; ti++) {
        if (ti < 15) { stage(cur ^ 1, l0base + (ti + 1) * 16); cpwait1(); }
        else cpwait0();
        __syncwarp();

        const float *ks = KS[h][cur];
        const float *vs = VS[h][cur];
        const float *crs = CRS[h][cur];
        float s[16];
#pragma unroll
        for (int jj = 0; jj < 16; jj++) {
            u64 a0 = pack2(0.f, 0.f), a1 = pack2(0.f, 0.f);
            const ulonglong2 *k2p = (const ulonglong2*)(ks + jj * 32);
#pragma unroll
            for (int j = 0; j < 8; j++) {
                ulonglong2 kk = k2p[j];
                ffma2(a0, q2[2 * j],     kk.x);
                ffma2(a1, q2[2 * j + 1], kk.y);
            }
            float x0, x1, y0, y1;
            unpack2(a0, x0, x1); unpack2(a1, y0, y1);
            float rp = w0 * crs[rr * 16 + jj] + w1 * crs[(rr + 1) * 16 + jj]
                     + w2 * crs[(rr + 2) * 16 + jj] + w3 * crs[(rr + 3) * 16 + jj];
            s[jj] = (x0 + y0) + (x1 + y1) + rp;
        }
        float mt = s[0];
#pragma unroll
        for (int jj = 1; jj < 16; jj++) mt = fmaxf(mt, s[jj]);
        if (mt > m) {
            float f = __expf(m - mt);
            sum *= f;
            u64 f2 = pack2(f, f);
#pragma unroll
            for (int t = 0; t < 16; t++) fscale2(O2[t], f2);
            m = mt;
        }
#pragma unroll
        for (int jj = 0; jj < 16; jj++) {
            float p = __expf(s[jj] - m);
            sum += p;
            u64 p2 = pack2(p, p);
            const ulonglong2 *v2p = (const ulonglong2*)(vs + jj * 32);
#pragma unroll
            for (int j = 0; j < 8; j++) {
                ulonglong2 vv = v2p[j];
                ffma2(O2[2 * j],     p2, vv.x);
                ffma2(O2[2 * j + 1], p2, vv.y);
            }
        }
        __syncwarp();
        cur ^= 1;
    }

    // write partials (coalesced: [b][h][chunk][t][n][4])
    int nc = br ? 8 : 2;
    float *pO = br ? g_pO2 : g_pO1;
    float *pm = br ? g_pm2 : g_pm1;
    float *ps = br ? g_ps2 : g_ps1;
    size_t cb = (size_t)(b * 4 + h) * nc + chunk;
    pm[cb * 4096 + n] = m;
    ps[cb * 4096 + n] = sum;
    float4 *op = (float4*)pO;
#pragma unroll
    for (int t = 0; t < 8; t++) {
        float a, bb, c, d;
        unpack2(O2[2 * t], a, bb);
        unpack2(O2[2 * t + 1], c, d);
        op[(cb * 8 + t) * 4096 + n] = make_float4(a, bb, c, d);
    }
}

// merge flash partials -> output
__global__ void __launch_bounds__(256) merge_k(float * __restrict__ out) {
    int idx = blockIdx.x * 256 + threadIdx.x;       // 65536
    int n = idx & 4095, h = (idx >> 12) & 3, br = (idx >> 14) & 1, b = idx >> 15;
    int nc = br ? 8 : 2;
    const float *pm = br ? g_pm2 : g_pm1;
    const float *ps = br ? g_ps2 : g_ps1;
    const float4 *pO = (const float4*)(br ? g_pO2 : g_pO1);
    size_t base = (size_t)(b * 4 + h) * nc;
    float M = -1e30f;
    for (int c = 0; c < nc; c++) M = fmaxf(M, pm[(base + c) * 4096 + n]);
    float S = 0.f;
    float4 acc[8] = {};
    for (int c = 0; c < nc; c++) {
        float w = __expf(pm[(base + c) * 4096 + n] - M);
        S += w * ps[(base + c) * 4096 + n];
#pragma unroll
        for (int t = 0; t < 8; t++) {
            float4 v = pO[((base + c) * 8 + t) * 4096 + n];
            acc[t].x += w * v.x; acc[t].y += w * v.y;
            acc[t].z += w * v.z; acc[t].w += w * v.w;
        }
    }
    float inv = 1.f / S;
    int ny = n >> 6, nx = n & 63;
    float4 *op = (float4*)(out + ((((size_t)b * 256 + h * 64 + ny) * 64 + nx) * 64 + br * 32));
#pragma unroll
    for (int t = 0; t < 8; t++)
        op[t] = make_float4(acc[t].x * inv, acc[t].y * inv, acc[t].z * inv, acc[t].w * inv);
}

extern "C" void kernel_launch(void* const* d_in, const int* in_sizes, int n_in,
                              void* d_out, int out_size) {
    const float *x    = (const float*)d_in[0];
    const float *rpe  = (const float*)d_in[1];
    const float *q_w  = (const float*)d_in[2];
    const float *q_b  = (const float*)d_in[3];
    const float *kv_w = (const float*)d_in[4];
    const float *kv_b = (const float*)d_in[5];
    const float *dw1  = (const float*)d_in[6];
    const float *bn11 = (const float*)d_in[7];
    const float *pw1  = (const float*)d_in[8];
    const float *bn12 = (const float*)d_in[9];
    const float *dw2  = (const float*)d_in[10];
    const float *bn21 = (const float*)d_in[11];
    const float *pw2  = (const float*)d_in[12];
    const float *bn22 = (const float*)d_in[13];
    const float *lw   = (const float*)d_in[14];
    const float *lb   = (const float*)d_in[15];
    float *out = (float*)d_out;

    rowtab_k<<<16, 256>>>();
    colres_k<<<256, 256>>>(rpe, 512, 0);
    colres_k<<<1024, 256>>>(rpe, 2048, 1);
    plane_k<7, 4, 3, 16, 0><<<512, 256>>>(x, dw1, bn11, pw1, bn12, lw, lb);
    plane_k<5, 2, 2, 32, 1><<<512, 256>>>(x, dw2, bn21, pw2, bn22, lw, lb);
    gemm_k<<<dim3(128, 2, 2), 128>>>(x, q_w, q_b, 0);
    gemm_k<<<dim3(8, 8, 2), 128>>>(x, kv_w, kv_b, 1);
    gemm_k<<<dim3(32, 8, 2), 128>>>(x, kv_w, kv_b, 2);
    attn_k<<<2560, 128>>>();
    merge_k<<<256, 256>>>(out);
}